// round 5
// baseline (speedup 1.0000x reference)
#include <cuda_runtime.h>
#include <math.h>
#include <math_constants.h>

#define N_NODES 50000
#define N_EDGES 1000000
#define F_IN    30
#define C       64
#define EDIM    11
#define G_GR    1024
#define D_OUT   256
#define NLAYERS 4

// ---------------- device scratch (static, allocation-free) ----------------
__device__ float    g_feat[N_NODES * C];     // layer input / aggregated output
__device__ float    g_hw[N_NODES * C];       // h = x @ W
__device__ float    g_res[N_NODES * C];      // x @ Wres + b
__device__ float    g_hs[N_NODES];
__device__ float    g_hd[N_NODES];
__device__ int      g_rowptr[N_NODES + 1];
__device__ int      g_cnt[N_NODES];
__device__ int      g_csr_src[N_EDGES];
__device__ int      g_perm[N_EDGES];
__device__ float    g_et[NLAYERS * N_EDGES]; // per-layer edge term, CSR order
__device__ float    g_aeff[NLAYERS * EDIM];  // We @ ae per layer

// ---------------- init: counters + aeff -----------------
__global__ void k_init(const float* __restrict__ We0, const float* __restrict__ ae0,
                       const float* __restrict__ We,  const float* __restrict__ ae) {
    int i = blockIdx.x * blockDim.x + threadIdx.x;
    if (i < N_NODES) g_cnt[i] = 0;
    if (i < NLAYERS * EDIM) {
        int l = i / EDIM, d = i % EDIM;
        const float* we = (l == 0) ? We0 : (We + (size_t)(l - 1) * EDIM * C);
        const float* av = (l == 0) ? ae0 : (ae + (size_t)(l - 1) * C);
        float s = 0.0f;
        #pragma unroll
        for (int c = 0; c < C; c++) s = fmaf(we[d * C + c], av[c], s);
        g_aeff[i] = s;
    }
}

// ---------------- CSR build ----------------
__global__ void k_hist(const int* __restrict__ edge_index) {
    int e = blockIdx.x * blockDim.x + threadIdx.x;
    if (e >= N_EDGES) return;
    int d = edge_index[N_EDGES + e];
    atomicAdd(&g_cnt[d], 1);
}

__global__ void k_scan() {
    __shared__ int wsum[32];
    const int T = 1024;
    int tid = threadIdx.x, lane = tid & 31, wid = tid >> 5;
    int chunk = (N_NODES + T - 1) / T;
    int beg = tid * chunk; if (beg > N_NODES) beg = N_NODES;
    int end = beg + chunk; if (end > N_NODES) end = N_NODES;
    int s = 0;
    for (int i = beg; i < end; i++) s += g_cnt[i];
    int v = s;
    #pragma unroll
    for (int o = 1; o < 32; o <<= 1) {
        int t = __shfl_up_sync(0xffffffffu, v, o);
        if (lane >= o) v += t;
    }
    if (lane == 31) wsum[wid] = v;
    __syncthreads();
    if (wid == 0) {
        int w = wsum[lane];
        #pragma unroll
        for (int o = 1; o < 32; o <<= 1) {
            int t = __shfl_up_sync(0xffffffffu, w, o);
            if (lane >= o) w += t;
        }
        wsum[lane] = w;
    }
    __syncthreads();
    int excl = (v - s) + ((wid > 0) ? wsum[wid - 1] : 0);
    int run = excl;
    for (int i = beg; i < end; i++) {
        int c = g_cnt[i];
        g_rowptr[i] = run;
        run += c;
        g_cnt[i] = 0;
    }
    if (tid == T - 1) g_rowptr[N_NODES] = run;
}

__global__ void k_scatter(const int* __restrict__ edge_index) {
    int e = blockIdx.x * blockDim.x + threadIdx.x;
    if (e >= N_EDGES) return;
    int s = edge_index[e];
    int d = edge_index[N_EDGES + e];
    int pos = g_rowptr[d] + atomicAdd(&g_cnt[d], 1);
    g_csr_src[pos] = s;
    g_perm[pos] = e;
}

// per-layer edge term et = edge_attr . (We@ae), written in CSR order
__global__ void k_et(const float* __restrict__ edge_attr) {
    int pos = blockIdx.x * blockDim.x + threadIdx.x;
    if (pos >= N_EDGES) return;
    int e = g_perm[pos];
    float ea[EDIM];
    #pragma unroll
    for (int j = 0; j < EDIM; j++) ea[j] = edge_attr[(size_t)e * EDIM + j];
    #pragma unroll
    for (int l = 0; l < NLAYERS; l++) {
        float s = 0.0f;
        #pragma unroll
        for (int j = 0; j < EDIM; j++) s = fmaf(ea[j], g_aeff[l * EDIM + j], s);
        g_et[(size_t)l * N_EDGES + pos] = s;
    }
}

// ---------------- fused node GEMM: h, res, hs, hd (4 rows per warp) --------
template <int F, bool FIRST>
__global__ void k_gemm(const float* __restrict__ xin, const float* __restrict__ W,
                       const float* __restrict__ Wres, const float* __restrict__ asrcv,
                       const float* __restrict__ adstv, const float* __restrict__ bv) {
    __shared__ float Ws[F * C];
    __shared__ float Wr[F * C];
    __shared__ float as_[C], ad_[C], bs_[C];
    int tid = threadIdx.x;
    for (int i = tid; i < F * C; i += 256) { Ws[i] = W[i]; Wr[i] = Wres[i]; }
    if (tid < C) { as_[tid] = asrcv[tid]; ad_[tid] = adstv[tid]; bs_[tid] = bv[tid]; }
    __syncthreads();
    int lane = tid & 31, wid = tid >> 5;
    #pragma unroll
    for (int r = 0; r < 4; r++) {
        int row = blockIdx.x * 32 + wid * 4 + r;
        if (row >= N_NODES) return;
        const float* xr = FIRST ? (xin + (size_t)row * F) : (g_feat + (size_t)row * F);
        float a0 = 0, a1 = 0, r0 = 0, r1 = 0;
        #pragma unroll
        for (int k = 0; k < F; k++) {
            float xv = xr[k];
            a0 = fmaf(xv, Ws[k * C + lane], a0);
            a1 = fmaf(xv, Ws[k * C + lane + 32], a1);
            r0 = fmaf(xv, Wr[k * C + lane], r0);
            r1 = fmaf(xv, Wr[k * C + lane + 32], r1);
        }
        size_t o = (size_t)row * C;
        g_hw[o + lane] = a0;
        g_hw[o + lane + 32] = a1;
        g_res[o + lane] = r0 + bs_[lane];
        g_res[o + lane + 32] = r1 + bs_[lane + 32];
        float p = a0 * as_[lane] + a1 * as_[lane + 32];
        float q = a0 * ad_[lane] + a1 * ad_[lane + 32];
        #pragma unroll
        for (int off = 16; off; off >>= 1) {
            p += __shfl_xor_sync(0xffffffffu, p, off);
            q += __shfl_xor_sync(0xffffffffu, q, off);
        }
        if (lane == 0) { g_hs[row] = p; g_hd[row] = q; }
    }
}

// ---------------- per-dst chunked softmax aggregation ----------------
// Lanes parallel over edges for alpha/exp; shfl-broadcast j-loop for h gather.
__global__ void k_agg(int layer, int act) {
    int d = blockIdx.x * 8 + (threadIdx.x >> 5);
    if (d >= N_NODES) return;
    int lane = threadIdx.x & 31;
    int beg = g_rowptr[d], end = g_rowptr[d + 1];
    float hdv = g_hd[d];
    const float* __restrict__ et = g_et + (size_t)layer * N_EDGES;
    float m = -CUDART_INF_F, s = 0.0f, acc0 = 0.0f, acc1 = 0.0f;

    for (int base = beg; base < end; base += 32) {
        int p = base + lane;
        bool valid = (p < end);
        int src = 0;
        float alpha = -CUDART_INF_F;
        if (valid) {
            src = g_csr_src[p];
            alpha = g_hs[src] + hdv + et[p];
            alpha = (alpha > 0.0f) ? alpha : 0.2f * alpha;   // leaky_relu 0.2
        }
        // warp max of this chunk
        float cmax = alpha;
        #pragma unroll
        for (int off = 16; off; off >>= 1)
            cmax = fmaxf(cmax, __shfl_xor_sync(0xffffffffu, cmax, off));
        float nm = fmaxf(m, cmax);
        float scale = __expf(m - nm);        // 0 on first chunk (m = -inf)
        float pe = valid ? __expf(alpha - nm) : 0.0f;
        // single rescale per chunk
        s *= scale; acc0 *= scale; acc1 *= scale;
        float psum = pe;
        #pragma unroll
        for (int off = 16; off; off >>= 1)
            psum += __shfl_xor_sync(0xffffffffu, psum, off);
        s += psum;
        int nval = end - base; if (nval > 32) nval = 32;
        for (int j = 0; j < nval; j++) {
            float pj = __shfl_sync(0xffffffffu, pe, j);
            int   sj = __shfl_sync(0xffffffffu, src, j);
            const float* hv = g_hw + (size_t)sj * C;
            acc0 = fmaf(pj, hv[lane], acc0);
            acc1 = fmaf(pj, hv[lane + 32], acc1);
        }
        m = nm;
    }

    float w = 1.0f / (s + 1e-16f);
    size_t o = (size_t)d * C;
    float o0 = acc0 * w + g_res[o + lane];
    float o1 = acc1 * w + g_res[o + lane + 32];
    if (act) {
        o0 = (o0 > 0.0f) ? o0 : 0.01f * o0;
        o1 = (o1 > 0.0f) ? o1 : 0.01f * o1;
    }
    g_feat[o + lane] = o0;
    g_feat[o + lane + 32] = o1;
}

// ---------------- fused pooling + final projection ----------------
// batch_index is sorted -> per-graph contiguous node range via binary search.
__global__ void k_out(const int* __restrict__ batch,
                      const float* __restrict__ Wout, const float* __restrict__ bout,
                      float* __restrict__ out) {
    int g = blockIdx.x;
    int t = threadIdx.x;  // 256 threads
    __shared__ int range[2];
    __shared__ float smx[4][C], ssm[4][C];
    __shared__ float pooled[2 * C];
    if (t == 0) {
        int lo = 0, hi = N_NODES;
        while (lo < hi) { int mid = (lo + hi) >> 1; if (batch[mid] < g) lo = mid + 1; else hi = mid; }
        range[0] = lo;
        lo = range[0]; hi = N_NODES;
        while (lo < hi) { int mid = (lo + hi) >> 1; if (batch[mid] < g + 1) lo = mid + 1; else hi = mid; }
        range[1] = lo;
    }
    __syncthreads();
    int start = range[0], endn = range[1];
    int c = t & 63, q = t >> 6;   // 4 node-strided partials per channel
    float mx = -CUDART_INF_F, sm = 0.0f;
    for (int n = start + q; n < endn; n += 4) {
        float v = g_feat[(size_t)n * C + c];
        mx = fmaxf(mx, v);
        sm += v;
    }
    smx[q][c] = mx; ssm[q][c] = sm;
    __syncthreads();
    if (t < C) {
        float M = fmaxf(fmaxf(smx[0][t], smx[1][t]), fmaxf(smx[2][t], smx[3][t]));
        float S = ssm[0][t] + ssm[1][t] + ssm[2][t] + ssm[3][t];
        if (!isfinite(M)) M = 0.0f;   // empty graph
        float cnt = (float)(endn - start); if (cnt < 1.0f) cnt = 1.0f;
        float mn = S / cnt;
        pooled[t]     = (M > 0.0f) ? M : 0.01f * M;
        pooled[C + t] = (mn > 0.0f) ? mn : 0.01f * mn;
    }
    __syncthreads();
    float acc = bout[t];
    #pragma unroll
    for (int k = 0; k < 2 * C; k++)
        acc = fmaf(pooled[k], Wout[(size_t)k * D_OUT + t], acc);
    out[(size_t)g * D_OUT + t] = acc;
}

// ---------------- launch ----------------
extern "C" void kernel_launch(void* const* d_in, const int* in_sizes, int n_in,
                              void* d_out, int out_size) {
    const float* x      = (const float*)d_in[0];
    const float* eattr  = (const float*)d_in[1];
    const float* W0     = (const float*)d_in[2];
    const float* asrc0  = (const float*)d_in[3];
    const float* adst0  = (const float*)d_in[4];
    const float* We0    = (const float*)d_in[5];
    const float* ae0    = (const float*)d_in[6];
    const float* Wres0  = (const float*)d_in[7];
    const float* b0     = (const float*)d_in[8];
    const float* W      = (const float*)d_in[9];
    const float* asrc   = (const float*)d_in[10];
    const float* adst   = (const float*)d_in[11];
    const float* We     = (const float*)d_in[12];
    const float* ae     = (const float*)d_in[13];
    const float* Wres   = (const float*)d_in[14];
    const float* b      = (const float*)d_in[15];
    const float* Wout   = (const float*)d_in[16];
    const float* bout   = (const float*)d_in[17];
    const int*   eidx   = (const int*)d_in[18];
    const int*   batch  = (const int*)d_in[19];
    float* out = (float*)d_out;

    const int EB   = (N_EDGES + 255) / 256;
    const int NB8  = (N_NODES + 7) / 8;
    const int NB32 = (N_NODES + 31) / 32;

    k_init<<<(N_NODES + 255) / 256, 256>>>(We0, ae0, We, ae);
    k_hist<<<EB, 256>>>(eidx);
    k_scan<<<1, 1024>>>();
    k_scatter<<<EB, 256>>>(eidx);
    k_et<<<EB, 256>>>(eattr);

    // layer 0 (F=30), leaky_relu 0.01 after
    k_gemm<F_IN, true><<<NB32, 256>>>(x, W0, Wres0, asrc0, adst0, b0);
    k_agg<<<NB8, 256>>>(0, 1);

    // layers 1..3 (F=64), activation after layers 1,2 only
    for (int i = 0; i < 3; i++) {
        k_gemm<C, false><<<NB32, 256>>>(nullptr,
                                        W + (size_t)i * C * C,
                                        Wres + (size_t)i * C * C,
                                        asrc + (size_t)i * C,
                                        adst + (size_t)i * C,
                                        b + (size_t)i * C);
        k_agg<<<NB8, 256>>>(i + 1, (i < 2) ? 1 : 0);
    }

    k_out<<<G_GR, D_OUT>>>(batch, Wout, bout, out);
}

// round 6
// speedup vs baseline: 1.9122x; 1.9122x over previous
#include <cuda_runtime.h>
#include <math.h>
#include <math_constants.h>

#define N_NODES 50000
#define N_EDGES 1000000
#define F_IN    30
#define C       64
#define EDIM    11
#define G_GR    1024
#define D_OUT   256
#define NLAYERS 4
#define SCAN_BLKS ((N_NODES + 255) / 256)   // 196

// ---------------- device scratch (static, allocation-free) ----------------
__device__ float    g_feat[N_NODES * C];     // layer input / aggregated output
__device__ float    g_hw[N_NODES * C];       // h = x @ W
__device__ float    g_res[N_NODES * C];      // x @ Wres + b
__device__ float    g_hs[N_NODES];
__device__ float    g_hd[N_NODES];
__device__ int      g_rowptr[N_NODES + 1];
__device__ int      g_cnt[N_NODES];
__device__ int2     g_edge[NLAYERS * N_EDGES]; // per-layer CSR: (src, et-bits)
__device__ float    g_aeff[NLAYERS * EDIM];    // We @ ae per layer
__device__ int      g_bsum[SCAN_BLKS];
__device__ int      g_boff[SCAN_BLKS];

// ---------------- init: counters + aeff -----------------
__global__ void k_init(const float* __restrict__ We0, const float* __restrict__ ae0,
                       const float* __restrict__ We,  const float* __restrict__ ae) {
    int i = blockIdx.x * blockDim.x + threadIdx.x;
    if (i < N_NODES) g_cnt[i] = 0;
    if (i < NLAYERS * EDIM) {
        int l = i / EDIM, d = i % EDIM;
        const float* we = (l == 0) ? We0 : (We + (size_t)(l - 1) * EDIM * C);
        const float* av = (l == 0) ? ae0 : (ae + (size_t)(l - 1) * C);
        float s = 0.0f;
        #pragma unroll
        for (int c = 0; c < C; c++) s = fmaf(we[d * C + c], av[c], s);
        g_aeff[i] = s;
    }
}

// ---------------- CSR build ----------------
__global__ void k_hist(const int* __restrict__ edge_index) {
    int e = blockIdx.x * blockDim.x + threadIdx.x;
    if (e >= N_EDGES) return;
    int d = edge_index[N_EDGES + e];
    atomicAdd(&g_cnt[d], 1);
}

// block-local exclusive scan of g_cnt -> g_rowptr, block totals -> g_bsum
__global__ void k_scanA() {
    __shared__ int wsum[8];
    int tid = threadIdx.x, lane = tid & 31, wid = tid >> 5;
    int i = blockIdx.x * 256 + tid;
    int c = (i < N_NODES) ? g_cnt[i] : 0;
    int inc = c;
    #pragma unroll
    for (int o = 1; o < 32; o <<= 1) {
        int t = __shfl_up_sync(0xffffffffu, inc, o);
        if (lane >= o) inc += t;
    }
    if (lane == 31) wsum[wid] = inc;
    __syncthreads();
    if (tid < 8) {
        int v = wsum[tid];
        #pragma unroll
        for (int o = 1; o < 8; o <<= 1) {
            int t = __shfl_up_sync(0x000000ffu, v, o);
            if ((tid & 7) >= o) v += t;
        }
        wsum[tid] = v;
    }
    __syncthreads();
    int excl = (inc - c) + ((wid > 0) ? wsum[wid - 1] : 0);
    if (i < N_NODES) { g_rowptr[i] = excl; g_cnt[i] = 0; }
    if (tid == 255) g_bsum[blockIdx.x] = wsum[7];
}

// single block: scan block sums -> g_boff, total -> rowptr[N]
__global__ void k_scanB() {
    __shared__ int s[256];
    int tid = threadIdx.x;
    s[tid] = (tid < SCAN_BLKS) ? g_bsum[tid] : 0;
    __syncthreads();
    for (int o = 1; o < 256; o <<= 1) {
        int t = (tid >= o) ? s[tid - o] : 0;
        __syncthreads();
        s[tid] += t;
        __syncthreads();
    }
    if (tid < SCAN_BLKS) g_boff[tid] = s[tid] - g_bsum[tid];  // exclusive
    if (tid == 0) g_rowptr[N_NODES] = s[SCAN_BLKS - 1];
}

__global__ void k_scanC() {
    int i = blockIdx.x * 256 + threadIdx.x;
    if (i < N_NODES) g_rowptr[i] += g_boff[blockIdx.x];
}

// ---------------- fused scatter + edge-term: (src, et_l) into CSR order ----
__global__ void k_scatter_et(const int* __restrict__ edge_index,
                             const float* __restrict__ edge_attr) {
    __shared__ float sa[NLAYERS * EDIM];
    __shared__ float sea[256 * EDIM];
    int tid = threadIdx.x;
    if (tid < NLAYERS * EDIM) sa[tid] = g_aeff[tid];
    int base = blockIdx.x * 256;
    int nE = N_EDGES - base; if (nE > 256) nE = 256;
    for (int i = tid; i < nE * EDIM; i += 256)
        sea[i] = edge_attr[(size_t)base * EDIM + i];
    __syncthreads();
    int e = base + tid;
    if (e >= N_EDGES) return;
    int s = edge_index[e];
    int d = edge_index[N_EDGES + e];
    int pos = g_rowptr[d] + atomicAdd(&g_cnt[d], 1);
    float ea[EDIM];
    #pragma unroll
    for (int j = 0; j < EDIM; j++) ea[j] = sea[tid * EDIM + j];
    #pragma unroll
    for (int l = 0; l < NLAYERS; l++) {
        float t = 0.0f;
        #pragma unroll
        for (int j = 0; j < EDIM; j++) t = fmaf(ea[j], sa[l * EDIM + j], t);
        g_edge[(size_t)l * N_EDGES + pos] = make_int2(s, __float_as_int(t));
    }
}

// ---------------- fused node GEMM: weights amortized over 4 rows/warp ------
template <int F, int FS, bool FIRST>
__global__ void k_gemm(const float* __restrict__ xin, const float* __restrict__ W,
                       const float* __restrict__ Wres, const float* __restrict__ asrcv,
                       const float* __restrict__ adstv, const float* __restrict__ bv) {
    __shared__ float Ws[F * C];
    __shared__ float Wr[F * C];
    __shared__ float xs[8][4][FS];
    __shared__ float as_[C], ad_[C], bs_[C];
    int tid = threadIdx.x;
    for (int i = tid; i < F * C; i += 256) { Ws[i] = W[i]; Wr[i] = Wres[i]; }
    if (tid < C) { as_[tid] = asrcv[tid]; ad_[tid] = adstv[tid]; bs_[tid] = bv[tid]; }
    int lane = tid & 31, wid = tid >> 5;
    int row0 = blockIdx.x * 32 + wid * 4;
    #pragma unroll
    for (int r = 0; r < 4; r++) {
        int row = row0 + r;
        if (row < N_NODES) {
            const float* xr = FIRST ? (xin + (size_t)row * F) : (g_feat + (size_t)row * F);
            if (lane < F) xs[wid][r][lane] = xr[lane];
            if (F > 32 && lane + 32 < F) xs[wid][r][lane + 32] = xr[lane + 32];
        }
    }
    __syncthreads();
    float a0[4] = {0, 0, 0, 0}, a1[4] = {0, 0, 0, 0};
    float r0[4] = {0, 0, 0, 0}, r1[4] = {0, 0, 0, 0};
    for (int k = 0; k < F; k++) {
        float ws0 = Ws[k * C + lane],  ws1 = Ws[k * C + lane + 32];
        float wr0 = Wr[k * C + lane],  wr1 = Wr[k * C + lane + 32];
        #pragma unroll
        for (int r = 0; r < 4; r++) {
            float xv = xs[wid][r][k];
            a0[r] = fmaf(xv, ws0, a0[r]);
            a1[r] = fmaf(xv, ws1, a1[r]);
            r0[r] = fmaf(xv, wr0, r0[r]);
            r1[r] = fmaf(xv, wr1, r1[r]);
        }
    }
    #pragma unroll
    for (int r = 0; r < 4; r++) {
        int row = row0 + r;
        if (row >= N_NODES) break;
        size_t o = (size_t)row * C;
        g_hw[o + lane] = a0[r];
        g_hw[o + lane + 32] = a1[r];
        g_res[o + lane] = r0[r] + bs_[lane];
        g_res[o + lane + 32] = r1[r] + bs_[lane + 32];
        float p = a0[r] * as_[lane] + a1[r] * as_[lane + 32];
        float q = a0[r] * ad_[lane] + a1[r] * ad_[lane + 32];
        #pragma unroll
        for (int off = 16; off; off >>= 1) {
            p += __shfl_xor_sync(0xffffffffu, p, off);
            q += __shfl_xor_sync(0xffffffffu, q, off);
        }
        if (lane == 0) { g_hs[row] = p; g_hd[row] = q; }
    }
}

// ---------------- per-dst chunked softmax aggregation ----------------
__global__ void k_agg(int layer, int act) {
    int d = blockIdx.x * 8 + (threadIdx.x >> 5);
    if (d >= N_NODES) return;
    int lane = threadIdx.x & 31;
    int beg = g_rowptr[d], end = g_rowptr[d + 1];
    float hdv = g_hd[d];
    const int2* __restrict__ ed = g_edge + (size_t)layer * N_EDGES;
    float m = -CUDART_INF_F, s = 0.0f, acc0 = 0.0f, acc1 = 0.0f;

    for (int base = beg; base < end; base += 32) {
        int p = base + lane;
        bool valid = (p < end);
        int src = 0;
        float alpha = -CUDART_INF_F;
        if (valid) {
            int2 v = ed[p];
            src = v.x;
            alpha = g_hs[src] + hdv + __int_as_float(v.y);
            alpha = (alpha > 0.0f) ? alpha : 0.2f * alpha;   // leaky_relu 0.2
        }
        float cmax = alpha;
        #pragma unroll
        for (int off = 16; off; off >>= 1)
            cmax = fmaxf(cmax, __shfl_xor_sync(0xffffffffu, cmax, off));
        float nm = fmaxf(m, cmax);
        float scale = __expf(m - nm);        // 0 on first chunk
        float pe = valid ? __expf(alpha - nm) : 0.0f;
        s *= scale; acc0 *= scale; acc1 *= scale;
        float psum = pe;
        #pragma unroll
        for (int off = 16; off; off >>= 1)
            psum += __shfl_xor_sync(0xffffffffu, psum, off);
        s += psum;
        int nval = end - base; if (nval > 32) nval = 32;
        for (int j = 0; j < nval; j++) {
            float pj = __shfl_sync(0xffffffffu, pe, j);
            int   sj = __shfl_sync(0xffffffffu, src, j);
            const float* hv = g_hw + (size_t)sj * C;
            acc0 = fmaf(pj, hv[lane], acc0);
            acc1 = fmaf(pj, hv[lane + 32], acc1);
        }
        m = nm;
    }

    float w = 1.0f / (s + 1e-16f);
    size_t o = (size_t)d * C;
    float o0 = acc0 * w + g_res[o + lane];
    float o1 = acc1 * w + g_res[o + lane + 32];
    if (act) {
        o0 = (o0 > 0.0f) ? o0 : 0.01f * o0;
        o1 = (o1 > 0.0f) ? o1 : 0.01f * o1;
    }
    g_feat[o + lane] = o0;
    g_feat[o + lane + 32] = o1;
}

// ---------------- fused pooling + final projection ----------------
__global__ void k_out(const int* __restrict__ batch,
                      const float* __restrict__ Wout, const float* __restrict__ bout,
                      float* __restrict__ out) {
    int g = blockIdx.x;
    int t = threadIdx.x;  // 256 threads
    __shared__ int range[2];
    __shared__ float smx[4][C], ssm[4][C];
    __shared__ float pooled[2 * C];
    if (t == 0) {
        int lo = 0, hi = N_NODES;
        while (lo < hi) { int mid = (lo + hi) >> 1; if (batch[mid] < g) lo = mid + 1; else hi = mid; }
        range[0] = lo;
        lo = range[0]; hi = N_NODES;
        while (lo < hi) { int mid = (lo + hi) >> 1; if (batch[mid] < g + 1) lo = mid + 1; else hi = mid; }
        range[1] = lo;
    }
    __syncthreads();
    int start = range[0], endn = range[1];
    int c = t & 63, q = t >> 6;
    float mx = -CUDART_INF_F, sm = 0.0f;
    for (int n = start + q; n < endn; n += 4) {
        float v = g_feat[(size_t)n * C + c];
        mx = fmaxf(mx, v);
        sm += v;
    }
    smx[q][c] = mx; ssm[q][c] = sm;
    __syncthreads();
    if (t < C) {
        float M = fmaxf(fmaxf(smx[0][t], smx[1][t]), fmaxf(smx[2][t], smx[3][t]));
        float S = ssm[0][t] + ssm[1][t] + ssm[2][t] + ssm[3][t];
        if (!isfinite(M)) M = 0.0f;   // empty graph
        float cnt = (float)(endn - start); if (cnt < 1.0f) cnt = 1.0f;
        float mn = S / cnt;
        pooled[t]     = (M > 0.0f) ? M : 0.01f * M;
        pooled[C + t] = (mn > 0.0f) ? mn : 0.01f * mn;
    }
    __syncthreads();
    float acc = bout[t];
    #pragma unroll
    for (int k = 0; k < 2 * C; k++)
        acc = fmaf(pooled[k], Wout[(size_t)k * D_OUT + t], acc);
    out[(size_t)g * D_OUT + t] = acc;
}

// ---------------- launch ----------------
extern "C" void kernel_launch(void* const* d_in, const int* in_sizes, int n_in,
                              void* d_out, int out_size) {
    const float* x      = (const float*)d_in[0];
    const float* eattr  = (const float*)d_in[1];
    const float* W0     = (const float*)d_in[2];
    const float* asrc0  = (const float*)d_in[3];
    const float* adst0  = (const float*)d_in[4];
    const float* We0    = (const float*)d_in[5];
    const float* ae0    = (const float*)d_in[6];
    const float* Wres0  = (const float*)d_in[7];
    const float* b0     = (const float*)d_in[8];
    const float* W      = (const float*)d_in[9];
    const float* asrc   = (const float*)d_in[10];
    const float* adst   = (const float*)d_in[11];
    const float* We     = (const float*)d_in[12];
    const float* ae     = (const float*)d_in[13];
    const float* Wres   = (const float*)d_in[14];
    const float* b      = (const float*)d_in[15];
    const float* Wout   = (const float*)d_in[16];
    const float* bout   = (const float*)d_in[17];
    const int*   eidx   = (const int*)d_in[18];
    const int*   batch  = (const int*)d_in[19];
    float* out = (float*)d_out;

    const int EB   = (N_EDGES + 255) / 256;
    const int NB8  = (N_NODES + 7) / 8;
    const int NB32 = (N_NODES + 31) / 32;

    k_init<<<(N_NODES + 255) / 256, 256>>>(We0, ae0, We, ae);
    k_hist<<<EB, 256>>>(eidx);
    k_scanA<<<SCAN_BLKS, 256>>>();
    k_scanB<<<1, 256>>>();
    k_scanC<<<SCAN_BLKS, 256>>>();
    k_scatter_et<<<EB, 256>>>(eidx, eattr);

    // layer 0 (F=30), leaky_relu 0.01 after
    k_gemm<F_IN, 32, true><<<NB32, 256>>>(x, W0, Wres0, asrc0, adst0, b0);
    k_agg<<<NB8, 256>>>(0, 1);

    // layers 1..3 (F=64), activation after layers 1,2 only
    for (int i = 0; i < 3; i++) {
        k_gemm<C, C, false><<<NB32, 256>>>(nullptr,
                                           W + (size_t)i * C * C,
                                           Wres + (size_t)i * C * C,
                                           asrc + (size_t)i * C,
                                           adst + (size_t)i * C,
                                           b + (size_t)i * C);
        k_agg<<<NB8, 256>>>(i + 1, (i < 2) ? 1 : 0);
    }

    k_out<<<G_GR, D_OUT>>>(batch, Wout, bout, out);
}